// round 9
// baseline (speedup 1.0000x reference)
#include <cuda_runtime.h>
#include <cstdint>

#define Bsz 1024
#define Tt  128
#define Dd  64
#define Hh  256
#define MB  8
#define NT  512
#define GRID 128
#define WER 352   // packed weight rows: 256 RK + 64 K_cc + 32 pad

typedef unsigned long long u64;

// ------------------- device scratch -------------------
__device__ float tdhT_g[Dd * Hh];                    // td_h_W^T  [k][c]
__device__ float tdxT_g[Dd * Dd];                    // td_x_W^T  [k][j]
__device__ float Gh_g[Bsz * Tt * Hh];                // gamma_h   [b*T+t][256]
__device__ float alpha_g[Bsz * Tt * Dd];             // alpha     [b*T+t][64]
__device__ float zprep_g[(Bsz / 2) * Tt * 1024 * 2]; // lstm_b + m@Wm, paired
__device__ float WE_g[WER * 1024];                   // packed LSTM weight stream

__device__ __forceinline__ u64 dup2(float w) {
    u64 r; asm("mov.b64 %0, {%1,%1};" : "=l"(r) : "f"(w)); return r;
}
__device__ __forceinline__ void upk2(u64 v, float& lo, float& hi) {
    asm("mov.b64 {%0,%1}, %2;" : "=f"(lo), "=f"(hi) : "l"(v));
}
__device__ __forceinline__ u64 fma2(u64 a, u64 b, u64 c) {
    u64 d; asm("fma.rn.f32x2 %0, %1, %2, %3;" : "=l"(d) : "l"(a), "l"(b), "l"(c)); return d;
}
__device__ __forceinline__ u64 add2(u64 a, u64 b) {
    u64 d; asm("add.rn.f32x2 %0, %1, %2;" : "=l"(d) : "l"(a), "l"(b)); return d;
}
__device__ __forceinline__ float sigf(float x) {
    return __fdividef(1.f, 1.f + __expf(-x));
}
__device__ __forceinline__ float tanhfast(float x) {
    return __fdividef(2.f, 1.f + __expf(-2.f * x)) - 1.f;
}

// ============================ precompute kernels ============================

__global__ void transpose_kernel(const float* __restrict__ tdhW,
                                 const float* __restrict__ tdxW) {
    int idx = blockIdx.x * 256 + threadIdx.x;
    if (idx < Hh * Dd) {                       // tdhW (256,64) -> [k][c]
        int c = idx >> 6, k = idx & 63;
        tdhT_g[k * Hh + c] = tdhW[idx];
    } else if (idx < Hh * Dd + Dd * Dd) {      // tdxW (64,64) -> [k][j]
        int e = idx - Hh * Dd;
        int j = e >> 6, k = e & 63;
        tdxT_g[k * Dd + j] = tdxW[e];
    }
}

// pack lstmRK rows 0..255, lstmK rows 0..63 at 256..319, zeros 320..351
__global__ void pack_we_kernel(const float* __restrict__ rk,
                               const float* __restrict__ kk) {
    int idx = blockIdx.x * 256 + threadIdx.x;
    if (idx >= WER * 1024) return;
    int r = idx >> 10, c = idx & 1023;
    float v = 0.f;
    if (r < 256)      v = rk[idx];
    else if (r < 320) v = kk[(r - 256) * 1024 + c];
    WE_g[idx] = v;
}

// gamma_h AND (gamma_x -> alpha): grid (128 batch-groups, 16 t-groups),
// weights staged once per block, reused over 8 t-steps.
__global__ void __launch_bounds__(256) pre_ga_kernel(
    const float* __restrict__ deltas, const float* __restrict__ masks,
    const float* __restrict__ tdhB, const float* __restrict__ tdxB,
    const float* __restrict__ wcW, const float* __restrict__ wcB)
{
    extern __shared__ float gsm[];
    float* tdh = gsm;                  // [64][256]
    float* tdx = tdh + 64 * 256;       // [64][64]
    float* wc  = tdx + 64 * 64;        // [128][64]
    float* dp  = wc + 128 * 64;        // [4][64][2]
    float* mp  = dp + 512;
    float* gxp = mp + 512;

    const int tid = threadIdx.x;
    const int bg  = blockIdx.x;        // batches bg*8..+8
    const int tg  = blockIdx.y;        // t's tg*8..+8

    for (int e = tid; e < 64 * 256; e += 256) tdh[e] = tdhT_g[e];
    for (int e = tid; e < 64 * 64; e += 256)  tdx[e] = tdxT_g[e];
    for (int e = tid; e < 128 * 64; e += 256) wc[e]  = wcW[e];
    const float bh = tdhB[tid];
    const float bx = tdxB[tid & 63];
    const float bw = wcB[tid & 63];

    for (int tt = 0; tt < 8; tt++) {
        const int tcur = tg * 8 + tt;
        __syncthreads();   // protects dp/mp reuse (and weight staging, 1st iter)
        for (int e = tid; e < 8 * Dd; e += 256) {
            int r = e >> 6, k = e & 63;
            int off = ((bg * 8 + r) * Tt + tcur) * Dd + k;
            dp[(r >> 1) * 128 + k * 2 + (r & 1)] = deltas[off];
            mp[(r >> 1) * 128 + k * 2 + (r & 1)] = masks[off];
        }
        __syncthreads();

        // ---- gamma_h: thread = column c ----
        {
            const int c = tid;
            u64 a[4];
            #pragma unroll
            for (int p = 0; p < 4; p++) a[p] = 0ULL;
            #pragma unroll 4
            for (int k = 0; k < Dd; k++) {
                u64 wd = dup2(tdh[k * Hh + c]);
                #pragma unroll
                for (int p = 0; p < 4; p++)
                    a[p] = fma2(*(const u64*)(dp + p * 128 + k * 2), wd, a[p]);
            }
            #pragma unroll
            for (int p = 0; p < 4; p++) {
                float a0, a1; upk2(a[p], a0, a1);
                Gh_g[((bg * 8 + 2 * p)     * Tt + tcur) * Hh + c] = __expf(-fmaxf(a0 + bh, 0.f));
                Gh_g[((bg * 8 + 2 * p + 1) * Tt + tcur) * Hh + c] = __expf(-fmaxf(a1 + bh, 0.f));
            }
        }

        // ---- gamma_x ----
        const int j = tid & 63, pg = tid >> 6;
        {
            u64 g = dup2(bx);
            #pragma unroll 4
            for (int k = 0; k < Dd; k++)
                g = fma2(*(const u64*)(dp + pg * 128 + k * 2), dup2(tdx[k * Dd + j]), g);
            float g0, g1; upk2(g, g0, g1);
            gxp[pg * 128 + j * 2 + 0] = __expf(-fmaxf(g0, 0.f));
            gxp[pg * 128 + j * 2 + 1] = __expf(-fmaxf(g1, 0.f));
        }
        __syncthreads();

        // ---- alpha ----
        {
            u64 al = dup2(bw);
            #pragma unroll 4
            for (int k = 0; k < Dd; k++) {
                al = fma2(*(const u64*)(gxp + pg * 128 + k * 2), dup2(wc[k * Dd + j]), al);
                al = fma2(*(const u64*)(mp  + pg * 128 + k * 2), dup2(wc[(Dd + k) * Dd + j]), al);
            }
            float a0, a1; upk2(al, a0, a1);
            alpha_g[((bg * 8 + 2 * pg)     * Tt + tcur) * Dd + j] = a0;
            alpha_g[((bg * 8 + 2 * pg + 1) * Tt + tcur) * Dd + j] = a1;
        }
    }
}

// zpre = lstm_b + m @ lstm_k[64:128], pair-interleaved (b even, b odd).
__global__ void __launch_bounds__(256) pre_z_kernel(
    const float* __restrict__ masks, const float* __restrict__ lstmK,
    const float* __restrict__ lstmB)
{
    extern __shared__ float psm[];
    float* W  = psm;               // [64][256]
    float* lb = W + 64 * 256;      // [256]
    float* mp = lb + 256;          // [16 t][64 k][2 par]
    const int tid = threadIdx.x;
    const int c0 = blockIdx.x * 256;
    const int bp = blockIdx.y;

    for (int e = tid; e < 64 * 256; e += 256) {
        int k = e >> 8, c = e & 255;
        W[e] = lstmK[(Dd + k) * 1024 + c0 + c];
    }
    lb[tid] = lstmB[c0 + tid];

    const int cq = tid & 63;
    const int pg = tid >> 6;

    for (int t0 = 0; t0 < Tt; t0 += 16) {
        __syncthreads();
        #pragma unroll
        for (int par = 0; par < 2; par++)
            for (int e = tid; e < 16 * 64; e += 256) {
                int tt = e >> 6, k = e & 63;
                mp[tt * 128 + k * 2 + par] =
                    masks[((2 * bp + par) * Tt + t0 + tt) * Dd + k];
            }
        __syncthreads();

        u64 acc[4][4];
        #pragma unroll
        for (int tt = 0; tt < 4; tt++)
            #pragma unroll
            for (int c = 0; c < 4; c++) acc[tt][c] = 0ULL;

        #pragma unroll 2
        for (int k = 0; k < Dd; k++) {
            float4 w = *(const float4*)(W + k * 256 + cq * 4);
            u64 w0 = dup2(w.x), w1 = dup2(w.y), w2 = dup2(w.z), w3 = dup2(w.w);
            #pragma unroll
            for (int tt = 0; tt < 4; tt++) {
                u64 m2 = *(const u64*)(mp + (pg * 4 + tt) * 128 + k * 2);
                acc[tt][0] = fma2(m2, w0, acc[tt][0]);
                acc[tt][1] = fma2(m2, w1, acc[tt][1]);
                acc[tt][2] = fma2(m2, w2, acc[tt][2]);
                acc[tt][3] = fma2(m2, w3, acc[tt][3]);
            }
        }
        float4 lbv = *(const float4*)(lb + cq * 4);
        u64 lb0 = dup2(lbv.x), lb1 = dup2(lbv.y), lb2 = dup2(lbv.z), lb3 = dup2(lbv.w);
        #pragma unroll
        for (int tt = 0; tt < 4; tt++) {
            int tg = t0 + pg * 4 + tt;
            int col = c0 + cq * 4;
            u64* dst = (u64*)(zprep_g + ((size_t)(bp * Tt + tg) * 1024 + col) * 2);
            dst[0] = add2(acc[tt][0], lb0);
            dst[1] = add2(acc[tt][1], lb1);
            dst[2] = add2(acc[tt][2], lb2);
            dst[3] = add2(acc[tt][3], lb3);
        }
    }
}

// ============================ main recurrent kernel ============================

struct __align__(16) Smem {
    float hist[Hh * Dd];      // 64 KB
    float frT[Dd * Dd];       // 16 KB
    float hp[4 * 2 * Hh];     //  8 KB  h paired [p][c*2+par]
    float cs[MB * Hh];        //  8 KB
    float zp[4 * 2 * 4 * Hh]; // 32 KB  gate acts (alias: x_h partials)
    float gh[MB * Hh];        //  8 KB  G_h[t+1] staging [r][c]
    float xs[MB * Dd], ms[MB * Dd];
    float alp[4 * 2 * Dd];
    float xcp[4 * 2 * Dd], xhp[4 * 2 * Dd], ccp[4 * 2 * Dd];
    float hist_b[Dd], fr_b[Dd];
};

template <int STRIDE>
__device__ __forceinline__ void eblk(const float* src, int k0,
                                     float2 w0, float2 w1, u64 (&acc)[4][2]) {
    u64 wa0 = dup2(w0.x), wb0 = dup2(w0.y);
    u64 wa1 = dup2(w1.x), wb1 = dup2(w1.y);
    #pragma unroll
    for (int p = 0; p < 4; p++) {
        float4 hv = *(const float4*)(src + p * STRIDE + k0 * 2);
        u64 h0 = ((const u64*)&hv)[0];
        u64 h1 = ((const u64*)&hv)[1];
        acc[p][0] = fma2(h0, wa0, acc[p][0]);
        acc[p][1] = fma2(h0, wb0, acc[p][1]);
        acc[p][0] = fma2(h1, wa1, acc[p][0]);
        acc[p][1] = fma2(h1, wb1, acc[p][1]);
    }
}

__global__ void __launch_bounds__(NT, 1) rits_kernel(
    const float* __restrict__ values, const float* __restrict__ masks,
    const float* __restrict__ histW, const float* __restrict__ histB,
    const float* __restrict__ frW, const float* __restrict__ frB,
    const float* __restrict__ outW, const float* __restrict__ outB,
    float* __restrict__ yout, float* __restrict__ impout)
{
    extern __shared__ char smem_raw[];
    Smem& sm = *reinterpret_cast<Smem*>(smem_raw);

    const int t  = threadIdx.x;
    const int b0 = blockIdx.x * MB;

    // ---- stage resident weights & init state ----
    for (int e = t; e < Hh * Dd; e += NT) sm.hist[e] = histW[e];
    for (int e = t; e < Dd * Dd; e += NT) {
        int k = e >> 6, jj = e & 63;
        sm.frT[e] = frW[jj * Dd + k];
    }
    if (t < Dd) { sm.hist_b[t] = histB[t]; sm.fr_b[t] = frB[t]; }
    for (int e = t; e < MB * Hh; e += NT) sm.cs[e] = 0.f;
    for (int e = t; e < 4 * 2 * Hh; e += NT) sm.hp[e] = 0.f;
    {   // step-0 inputs + alpha[0]
        int r = t >> 6, jj = t & 63;
        int off = ((b0 + r) * Tt + 0) * Dd + jj;
        sm.xs[t] = values[off]; sm.ms[t] = masks[off];
        int j = t & 63, p = (t >> 6) & 3, par = t >> 8;
        sm.alp[p * 128 + j * 2 + par] = alpha_g[((b0 + 2 * p + par) * Tt + 0) * Dd + j];
    }
    __syncthreads();

    float pf_x[2], pf_m[2], pf_a0, pf_a1;   // wg1 prefetch regs

    for (int step = 0; step < Tt; ++step) {
        // ---- P1 (all): x_h partials, k-split 8-way, into zp alias ----
        float2* cpart = (float2*)sm.zp;
        {
            const int j = t & 63, kq = t >> 6;
            u64 a[4];
            #pragma unroll
            for (int p = 0; p < 4; p++) a[p] = 0ULL;
            const int k0 = kq * 32;
            #pragma unroll 4
            for (int kk = 0; kk < 32; kk++) {
                int k = k0 + kk;
                u64 wd = dup2(sm.hist[k * Dd + j]);
                #pragma unroll
                for (int p = 0; p < 4; p++)
                    a[p] = fma2(*(const u64*)(sm.hp + p * 512 + k * 2), wd, a[p]);
            }
            #pragma unroll
            for (int p = 0; p < 4; p++) {
                float a0, a1; upk2(a[p], a0, a1);
                cpart[(kq * 4 + p) * 64 + j] = make_float2(a0, a1);
            }
        }
        __syncthreads();

        // ---- P3: wg0 {reduce -> x_c; z_h -> c_c -> impout} | wg1 {prefetch} --
        if (t < 256) {
            const int j = t & 63, p = t >> 6;
            const float* cp = (const float*)cpart;
            float xh[2];
            #pragma unroll
            for (int par = 0; par < 2; par++) {
                float s = 0.f;
                #pragma unroll
                for (int kq = 0; kq < 8; kq++)
                    s += cp[((kq * 4 + p) * 64 + j) * 2 + par];
                xh[par] = s + sm.hist_b[j];
                int r = 2 * p + par;
                float m = sm.ms[r * Dd + j], x = sm.xs[r * Dd + j];
                float xc = m * x + (1.f - m) * xh[par];
                sm.xcp[p * 128 + j * 2 + par] = xc;
                sm.xhp[p * 128 + j * 2 + par] = xh[par];
            }
            asm volatile("bar.sync 1, 256;" ::: "memory");
            u64 z = dup2(sm.fr_b[j]);
            #pragma unroll 4
            for (int k = 0; k < Dd; k++)
                z = fma2(*(const u64*)(sm.xcp + p * 128 + k * 2),
                         dup2(sm.frT[k * Dd + j]), z);
            float z0, z1; upk2(z, z0, z1);
            float2 al = *(const float2*)(sm.alp + p * 128 + j * 2);
            int r0 = 2 * p, r1 = r0 + 1;
            float m0 = sm.ms[r0 * Dd + j], m1 = sm.ms[r1 * Dd + j];
            float x0 = sm.xs[r0 * Dd + j], x1 = sm.xs[r1 * Dd + j];
            float ch0 = al.x * z0 + (1.f - al.x) * xh[0];
            float ch1 = al.y * z1 + (1.f - al.y) * xh[1];
            float cc0 = m0 * x0 + (1.f - m0) * ch0;
            float cc1 = m1 * x1 + (1.f - m1) * ch1;
            *(float2*)(sm.ccp + p * 128 + j * 2) = make_float2(cc0, cc1);
            impout[(r0 + b0) * Tt * Dd + step * Dd + j] = cc0;
            impout[(r1 + b0) * Tt * Dd + step * Dd + j] = cc1;
        } else if (step + 1 < Tt) {
            const int u = t - 256;
            #pragma unroll
            for (int s = 0; s < 2; s++) {
                int e = u + s * 256;
                int r = e >> 6, jj = e & 63;
                int off = ((b0 + r) * Tt + (step + 1)) * Dd + jj;
                pf_x[s] = values[off]; pf_m[s] = masks[off];
            }
            {
                int j = u & 63, rp = u >> 6;
                pf_a0 = alpha_g[((b0 + 2 * rp)     * Tt + step + 1) * Dd + j];
                pf_a1 = alpha_g[((b0 + 2 * rp + 1) * Tt + step + 1) * Dd + j];
            }
            {
                int r = u >> 5, c0 = (u & 31) * 8;
                const float* gsrc = Gh_g + ((b0 + r) * Tt + (step + 1)) * Hh + c0;
                float4 g0 = *(const float4*)gsrc;
                float4 g1 = *(const float4*)(gsrc + 4);
                *(float4*)(sm.gh + r * Hh + c0)     = g0;
                *(float4*)(sm.gh + r * Hh + c0 + 4) = g1;
            }
        }
        __syncthreads();

        // ---- P4 (all): z = zpre + h@Wrk + c_c@Wk over packed WE_g,
        //      single pointer walk, distance-16 prefetch, no masks ----
        {
            u64 acc[4][2];
            #pragma unroll
            for (int p = 0; p < 4; p++) { acc[p][0] = 0ULL; acc[p][1] = 0ULL; }

            const float2* wpt = (const float2*)WE_g + t;   // row stride 512 float2
            float2 wa[8], wb[8];
            #pragma unroll
            for (int i = 0; i < 8; i++) wa[i] = wpt[i * 512];
            #pragma unroll
            for (int i = 0; i < 8; i++) wb[i] = wpt[(8 + i) * 512];
            const float2* wpf = wpt + 16 * 512;            // prefetch ptr: row k+16

            // recurrent section: rows 0..255, operand hp
            #pragma unroll 1
            for (int k = 0; k < Hh; k += 16) {
                eblk<512>(sm.hp, k,      wa[0], wa[1], acc);
                eblk<512>(sm.hp, k + 2,  wa[2], wa[3], acc);
                eblk<512>(sm.hp, k + 4,  wa[4], wa[5], acc);
                eblk<512>(sm.hp, k + 6,  wa[6], wa[7], acc);
                #pragma unroll
                for (int i = 0; i < 8; i++) wa[i] = wpf[i * 512];
                wpf += 8 * 512;
                eblk<512>(sm.hp, k + 8,  wb[0], wb[1], acc);
                eblk<512>(sm.hp, k + 10, wb[2], wb[3], acc);
                eblk<512>(sm.hp, k + 12, wb[4], wb[5], acc);
                eblk<512>(sm.hp, k + 14, wb[6], wb[7], acc);
                #pragma unroll
                for (int i = 0; i < 8; i++) wb[i] = wpf[i * 512];
                wpf += 8 * 512;
            }
            // cc section: rows 256..319 (= cc k2 0..63), operand ccp;
            // wa/wb already hold rows 256..271 from the tail prefetch above
            #pragma unroll 1
            for (int k2 = 0; k2 < Dd; k2 += 16) {
                eblk<128>(sm.ccp, k2,      wa[0], wa[1], acc);
                eblk<128>(sm.ccp, k2 + 2,  wa[2], wa[3], acc);
                eblk<128>(sm.ccp, k2 + 4,  wa[4], wa[5], acc);
                eblk<128>(sm.ccp, k2 + 6,  wa[6], wa[7], acc);
                #pragma unroll
                for (int i = 0; i < 8; i++) wa[i] = wpf[i * 512];
                wpf += 8 * 512;
                eblk<128>(sm.ccp, k2 + 8,  wb[0], wb[1], acc);
                eblk<128>(sm.ccp, k2 + 10, wb[2], wb[3], acc);
                eblk<128>(sm.ccp, k2 + 12, wb[4], wb[5], acc);
                eblk<128>(sm.ccp, k2 + 14, wb[6], wb[7], acc);
                #pragma unroll
                for (int i = 0; i < 8; i++) wb[i] = wpf[i * 512];
                wpf += 8 * 512;
            }

            // epilogue: zpre + activations
            const float4* zp4 = (const float4*)zprep_g;
            const int gate = t >> 7;
            #pragma unroll
            for (int p = 0; p < 4; p++) {
                float4 v = zp4[((size_t)(b0 / 2 + p) * Tt + step) * 512 + t];
                u64 zi0 = ((const u64*)&v)[0];
                u64 zi1 = ((const u64*)&v)[1];
                #pragma unroll
                for (int q = 0; q < 2; q++) {
                    u64 zv = add2(acc[p][q], q ? zi1 : zi0);
                    float v0, v1; upk2(zv, v0, v1);
                    float b0f, b1f;
                    if (gate == 2) { b0f = tanhfast(v0); b1f = tanhfast(v1); }
                    else           { b0f = sigf(v0);     b1f = sigf(v1);     }
                    int col = 2 * t + q;
                    *(float2*)(sm.zp + p * 2048 + col * 2) = make_float2(b0f, b1f);
                }
            }
        }
        __syncthreads();

        // ---- P5: wg0 {c,h update + fused next-step decay} | wg1 {commit} ----
        if (t < 256) {
            int r = t >> 5;
            int p = r >> 1, par = r & 1;
            int cb = (t & 31) * 8;
            bool last = (step == Tt - 1);
            float4 gA = *(const float4*)(sm.gh + r * Hh + cb);
            float4 gB = *(const float4*)(sm.gh + r * Hh + cb + 4);
            float gv8[8] = {gA.x, gA.y, gA.z, gA.w, gB.x, gB.y, gB.z, gB.w};
            #pragma unroll
            for (int cc = 0; cc < 8; cc++) {
                int c = cb + cc;
                float iv = sm.zp[p * 2048 + (0 * Hh + c) * 2 + par];
                float fv = sm.zp[p * 2048 + (1 * Hh + c) * 2 + par];
                float gg = sm.zp[p * 2048 + (2 * Hh + c) * 2 + par];
                float ov = sm.zp[p * 2048 + (3 * Hh + c) * 2 + par];
                float cold = sm.cs[r * Hh + c];
                float cnew = fv * cold + iv * gg;
                sm.cs[r * Hh + c] = cnew;
                float hh = ov * tanhfast(cnew);
                if (!last) hh *= gv8[cc];
                sm.hp[p * 512 + c * 2 + par] = hh;
            }
        } else if (step + 1 < Tt) {
            const int u = t - 256;
            #pragma unroll
            for (int s = 0; s < 2; s++) {
                int e = u + s * 256;
                sm.xs[e] = pf_x[s]; sm.ms[e] = pf_m[s];
            }
            int j = u & 63, rp = u >> 6;
            *(float2*)(sm.alp + rp * 128 + j * 2) = make_float2(pf_a0, pf_a1);
        }
        __syncthreads();
    }

    // ---- final: y = h @ out_W + out_b ----
    {
        int w = t >> 5, lane = t & 31;
        if (w < MB) {
            float s = 0.f;
            for (int k = lane; k < Hh; k += 32)
                s += sm.hp[(w >> 1) * 512 + k * 2 + (w & 1)] * outW[k];
            #pragma unroll
            for (int o = 16; o > 0; o >>= 1)
                s += __shfl_down_sync(0xffffffffu, s, o);
            if (lane == 0) yout[b0 + w] = s + outB[0];
        }
    }
}

// ================================ launcher ================================

extern "C" void kernel_launch(void* const* d_in, const int* in_sizes, int n_in,
                              void* d_out, int out_size) {
    const float* values = (const float*)d_in[0];
    const float* masks  = (const float*)d_in[1];
    const float* deltas = (const float*)d_in[2];
    const float* tdhW   = (const float*)d_in[3];
    const float* tdhB   = (const float*)d_in[4];
    const float* tdxW   = (const float*)d_in[5];
    const float* tdxB   = (const float*)d_in[6];
    const float* histW  = (const float*)d_in[7];
    const float* histB  = (const float*)d_in[8];
    const float* frW    = (const float*)d_in[9];
    const float* frB    = (const float*)d_in[10];
    const float* wcW    = (const float*)d_in[11];
    const float* wcB    = (const float*)d_in[12];
    const float* lstmK  = (const float*)d_in[13];
    const float* lstmRK = (const float*)d_in[14];
    const float* lstmB  = (const float*)d_in[15];
    const float* outW   = (const float*)d_in[16];
    const float* outB   = (const float*)d_in[17];

    float* yout   = (float*)d_out;       // y_h [B,1] first
    float* impout = yout + Bsz;          // imputations [B,T,D]

    transpose_kernel<<<(Hh * Dd + Dd * Dd + 255) / 256, 256>>>(tdhW, tdxW);
    pack_we_kernel<<<(WER * 1024 + 255) / 256, 256>>>(lstmRK, lstmK);

    int gasm = (64 * 256 + 64 * 64 + 128 * 64 + 3 * 512) * 4;   // ~118 KB
    cudaFuncSetAttribute(pre_ga_kernel, cudaFuncAttributeMaxDynamicSharedMemorySize, gasm);
    pre_ga_kernel<<<dim3(Bsz / 8, Tt / 8), 256, gasm>>>(deltas, masks, tdhB, tdxB, wcW, wcB);

    int zsm = (64 * 256 + 256 + 16 * 128) * 4;   // ~73 KB
    cudaFuncSetAttribute(pre_z_kernel, cudaFuncAttributeMaxDynamicSharedMemorySize, zsm);
    pre_z_kernel<<<dim3(4, Bsz / 2), 256, zsm>>>(masks, lstmK, lstmB);

    cudaFuncSetAttribute(rits_kernel, cudaFuncAttributeMaxDynamicSharedMemorySize,
                         (int)sizeof(Smem));
    rits_kernel<<<GRID, NT, sizeof(Smem)>>>(
        values, masks, histW, histB, frW, frB,
        outW, outB, yout, impout);
}

// round 10
// speedup vs baseline: 1.1366x; 1.1366x over previous
#include <cuda_runtime.h>
#include <cstdint>

#define Bsz 1024
#define Tt  128
#define Dd  64
#define Hh  256
#define MB  8
#define NT  512
#define GRID 128

typedef unsigned long long u64;

// ------------------- device scratch -------------------
__device__ float tdhT_g[Dd * Hh];        // td_h_W^T  [k][c]
__device__ float tdxT_g[Dd * Dd];        // td_x_W^T  [k][j]
__device__ float Gh_g[Bsz * Tt * Hh];    // gamma_h   [b*T+t][256]
__device__ float alpha_g[Bsz * Tt * Dd]; // alpha     [b*T+t][64]

__device__ __forceinline__ u64 dup2(float w) {
    u64 r; asm("mov.b64 %0, {%1,%1};" : "=l"(r) : "f"(w)); return r;
}
__device__ __forceinline__ void upk2(u64 v, float& lo, float& hi) {
    asm("mov.b64 {%0,%1}, %2;" : "=f"(lo), "=f"(hi) : "l"(v));
}
__device__ __forceinline__ u64 fma2(u64 a, u64 b, u64 c) {
    u64 d; asm("fma.rn.f32x2 %0, %1, %2, %3;" : "=l"(d) : "l"(a), "l"(b), "l"(c)); return d;
}
__device__ __forceinline__ float sigf(float x) {
    return __fdividef(1.f, 1.f + __expf(-x));
}
__device__ __forceinline__ float tanhfast(float x) {
    return __fdividef(2.f, 1.f + __expf(-2.f * x)) - 1.f;
}

// ============================ precompute kernels ============================

__global__ void transpose_kernel(const float* __restrict__ tdhW,
                                 const float* __restrict__ tdxW) {
    int idx = blockIdx.x * 256 + threadIdx.x;
    if (idx < Hh * Dd) {                       // tdhW (256,64) -> [k][c]
        int c = idx >> 6, k = idx & 63;
        tdhT_g[k * Hh + c] = tdhW[idx];
    } else if (idx < Hh * Dd + Dd * Dd) {      // tdxW (64,64) -> [k][j]
        int e = idx - Hh * Dd;
        int j = e >> 6, k = e & 63;
        tdxT_g[k * Dd + j] = tdxW[e];
    }
}

// merged: gamma_h AND (gamma_x -> alpha) for 8 rows/CTA (shares delta/mask loads)
__global__ void __launch_bounds__(256) pre_ga_kernel(
    const float* __restrict__ deltas, const float* __restrict__ masks,
    const float* __restrict__ tdhB, const float* __restrict__ tdxB,
    const float* __restrict__ wcW, const float* __restrict__ wcB)
{
    __shared__ float dp[4 * Dd * 2], mp[4 * Dd * 2], gxp[4 * Dd * 2];
    const int tid = threadIdx.x;
    const int row0 = blockIdx.x * 8;
    for (int e = tid; e < 8 * Dd; e += 256) {
        int r = e >> 6, k = e & 63;
        dp[(r >> 1) * 128 + k * 2 + (r & 1)] = deltas[(row0 + r) * Dd + k];
        mp[(r >> 1) * 128 + k * 2 + (r & 1)] = masks[(row0 + r) * Dd + k];
    }
    __syncthreads();

    // ---- gamma_h: each thread one column c ----
    {
        const int c = tid;
        u64 a[4];
        #pragma unroll
        for (int p = 0; p < 4; p++) a[p] = 0ULL;
        #pragma unroll 4
        for (int k = 0; k < Dd; k++) {
            u64 wd = dup2(tdhT_g[k * Hh + c]);
            #pragma unroll
            for (int p = 0; p < 4; p++)
                a[p] = fma2(*(const u64*)(dp + p * 128 + k * 2), wd, a[p]);
        }
        float bb = tdhB[c];
        #pragma unroll
        for (int p = 0; p < 4; p++) {
            float a0, a1; upk2(a[p], a0, a1);
            Gh_g[(row0 + 2 * p)     * Hh + c] = __expf(-fmaxf(a0 + bb, 0.f));
            Gh_g[(row0 + 2 * p + 1) * Hh + c] = __expf(-fmaxf(a1 + bb, 0.f));
        }
    }

    // ---- gamma_x then alpha ----
    const int j = tid & 63, pg = tid >> 6;
    u64 g = dup2(tdxB[j]);
    #pragma unroll 4
    for (int k = 0; k < Dd; k++)
        g = fma2(*(const u64*)(dp + pg * 128 + k * 2), dup2(tdxT_g[k * Dd + j]), g);
    float g0, g1; upk2(g, g0, g1);
    gxp[pg * 128 + j * 2 + 0] = __expf(-fmaxf(g0, 0.f));
    gxp[pg * 128 + j * 2 + 1] = __expf(-fmaxf(g1, 0.f));
    __syncthreads();
    u64 al = dup2(wcB[j]);
    #pragma unroll 4
    for (int k = 0; k < Dd; k++) {
        al = fma2(*(const u64*)(gxp + pg * 128 + k * 2), dup2(wcW[k * Dd + j]), al);
        al = fma2(*(const u64*)(mp  + pg * 128 + k * 2), dup2(wcW[(Dd + k) * Dd + j]), al);
    }
    float a0, a1; upk2(al, a0, a1);
    alpha_g[(row0 + 2 * pg)     * Dd + j] = a0;
    alpha_g[(row0 + 2 * pg + 1) * Dd + j] = a1;
}

// ============================ main recurrent kernel ============================

struct __align__(16) Smem {
    float hist[Hh * Dd];      // 64 KB
    float frT[Dd * Dd];       // 16 KB
    float hp[4 * 2 * Hh];     //  8 KB  h paired [p][c*2+par]
    float cs[MB * Hh];        //  8 KB
    float zp[4 * 2 * 4 * Hh]; // 32 KB  gate acts (alias: x_h partials)
    float gh[MB * Hh];        //  8 KB  G_h[t+1] staging [r][c]
    float xs[MB * Dd], ms[MB * Dd];
    float mp[4 * 2 * Dd];     // paired m  [p][k*2+par]
    float alp[4 * 2 * Dd];
    float xcp[4 * 2 * Dd], xhp[4 * 2 * Dd], ccp[4 * 2 * Dd];
    float hist_b[Dd], fr_b[Dd];
};

template <int STRIDE>
__device__ __forceinline__ void eblk(const float* src, int k0,
                                     float2 w0, float2 w1, u64 (&acc)[4][2]) {
    u64 wa0 = dup2(w0.x), wb0 = dup2(w0.y);
    u64 wa1 = dup2(w1.x), wb1 = dup2(w1.y);
    #pragma unroll
    for (int p = 0; p < 4; p++) {
        float4 hv = *(const float4*)(src + p * STRIDE + k0 * 2);
        u64 h0 = ((const u64*)&hv)[0];
        u64 h1 = ((const u64*)&hv)[1];
        acc[p][0] = fma2(h0, wa0, acc[p][0]);
        acc[p][1] = fma2(h0, wb0, acc[p][1]);
        acc[p][0] = fma2(h1, wa1, acc[p][0]);
        acc[p][1] = fma2(h1, wb1, acc[p][1]);
    }
}

__global__ void __launch_bounds__(NT, 1) rits_kernel(
    const float* __restrict__ values, const float* __restrict__ masks,
    const float* __restrict__ histW, const float* __restrict__ histB,
    const float* __restrict__ frW, const float* __restrict__ frB,
    const float* __restrict__ lstmK, const float* __restrict__ lstmRK,
    const float* __restrict__ lstmB,
    const float* __restrict__ outW, const float* __restrict__ outB,
    float* __restrict__ yout, float* __restrict__ impout)
{
    extern __shared__ char smem_raw[];
    Smem& sm = *reinterpret_cast<Smem*>(smem_raw);

    const int t  = threadIdx.x;
    const int b0 = blockIdx.x * MB;

    // ---- stage resident weights & init state ----
    for (int e = t; e < Hh * Dd; e += NT) sm.hist[e] = histW[e];
    for (int e = t; e < Dd * Dd; e += NT) {
        int k = e >> 6, jj = e & 63;
        sm.frT[e] = frW[jj * Dd + k];
    }
    if (t < Dd) { sm.hist_b[t] = histB[t]; sm.fr_b[t] = frB[t]; }
    for (int e = t; e < MB * Hh; e += NT) sm.cs[e] = 0.f;
    for (int e = t; e < 4 * 2 * Hh; e += NT) sm.hp[e] = 0.f;
    {   // step-0 inputs + alpha[0]
        int r = t >> 6, jj = t & 63;
        int off = ((b0 + r) * Tt + 0) * Dd + jj;
        float xv = values[off], mv = masks[off];
        sm.xs[t] = xv; sm.ms[t] = mv;
        sm.mp[(r >> 1) * 128 + jj * 2 + (r & 1)] = mv;
        int j = t & 63, p = (t >> 6) & 3, par = t >> 8;
        sm.alp[p * 128 + j * 2 + par] = alpha_g[((b0 + 2 * p + par) * Tt + 0) * Dd + j];
    }
    // LSTM bias for this thread's two output columns (cols 2t, 2t+1)
    const u64 bq0 = dup2(lstmB[2 * t]);
    const u64 bq1 = dup2(lstmB[2 * t + 1]);
    __syncthreads();

    float pf_x[2], pf_m[2], pf_a0, pf_a1;   // wg1 prefetch regs

    for (int step = 0; step < Tt; ++step) {
        // ---- P1 (all): x_h partials, k-split 8-way, into zp alias ----
        float2* cpart = (float2*)sm.zp;
        {
            const int j = t & 63, kq = t >> 6;
            u64 a[4];
            #pragma unroll
            for (int p = 0; p < 4; p++) a[p] = 0ULL;
            const int k0 = kq * 32;
            #pragma unroll 4
            for (int kk = 0; kk < 32; kk++) {
                int k = k0 + kk;
                u64 wd = dup2(sm.hist[k * Dd + j]);
                #pragma unroll
                for (int p = 0; p < 4; p++)
                    a[p] = fma2(*(const u64*)(sm.hp + p * 512 + k * 2), wd, a[p]);
            }
            #pragma unroll
            for (int p = 0; p < 4; p++) {
                float a0, a1; upk2(a[p], a0, a1);
                cpart[(kq * 4 + p) * 64 + j] = make_float2(a0, a1);
            }
        }
        __syncthreads();

        // ---- P3: wg0 {reduce -> x_c; z_h -> c_c -> impout} | wg1 {prefetch} --
        if (t < 256) {
            const int j = t & 63, p = t >> 6;
            const float* cp = (const float*)cpart;
            float xh[2];
            #pragma unroll
            for (int par = 0; par < 2; par++) {
                float s = 0.f;
                #pragma unroll
                for (int kq = 0; kq < 8; kq++)
                    s += cp[((kq * 4 + p) * 64 + j) * 2 + par];
                xh[par] = s + sm.hist_b[j];
                int r = 2 * p + par;
                float m = sm.ms[r * Dd + j], x = sm.xs[r * Dd + j];
                float xc = m * x + (1.f - m) * xh[par];
                sm.xcp[p * 128 + j * 2 + par] = xc;
                sm.xhp[p * 128 + j * 2 + par] = xh[par];
            }
            asm volatile("bar.sync 1, 256;" ::: "memory");
            u64 z = dup2(sm.fr_b[j]);
            #pragma unroll 4
            for (int k = 0; k < Dd; k++)
                z = fma2(*(const u64*)(sm.xcp + p * 128 + k * 2),
                         dup2(sm.frT[k * Dd + j]), z);
            float z0, z1; upk2(z, z0, z1);
            float2 al = *(const float2*)(sm.alp + p * 128 + j * 2);
            int r0 = 2 * p, r1 = r0 + 1;
            float m0 = sm.ms[r0 * Dd + j], m1 = sm.ms[r1 * Dd + j];
            float x0 = sm.xs[r0 * Dd + j], x1 = sm.xs[r1 * Dd + j];
            float ch0 = al.x * z0 + (1.f - al.x) * xh[0];
            float ch1 = al.y * z1 + (1.f - al.y) * xh[1];
            float cc0 = m0 * x0 + (1.f - m0) * ch0;
            float cc1 = m1 * x1 + (1.f - m1) * ch1;
            *(float2*)(sm.ccp + p * 128 + j * 2) = make_float2(cc0, cc1);
            impout[(r0 + b0) * Tt * Dd + step * Dd + j] = cc0;
            impout[(r1 + b0) * Tt * Dd + step * Dd + j] = cc1;
        } else if (step + 1 < Tt) {
            const int u = t - 256;
            #pragma unroll
            for (int s = 0; s < 2; s++) {
                int e = u + s * 256;
                int r = e >> 6, jj = e & 63;
                int off = ((b0 + r) * Tt + (step + 1)) * Dd + jj;
                pf_x[s] = values[off]; pf_m[s] = masks[off];
            }
            {
                int j = u & 63, rp = u >> 6;
                pf_a0 = alpha_g[((b0 + 2 * rp)     * Tt + step + 1) * Dd + j];
                pf_a1 = alpha_g[((b0 + 2 * rp + 1) * Tt + step + 1) * Dd + j];
            }
            {
                int r = u >> 5, c0 = (u & 31) * 8;
                const float* gsrc = Gh_g + ((b0 + r) * Tt + (step + 1)) * Hh + c0;
                float4 g0 = *(const float4*)gsrc;
                float4 g1 = *(const float4*)(gsrc + 4);
                *(float4*)(sm.gh + r * Hh + c0)     = g0;
                *(float4*)(sm.gh + r * Hh + c0 + 4) = g1;
            }
        }
        __syncthreads();

        // ---- P4 (all): z = b + h@Wrk + c_c@Wk_cc + m@Wk_m ; dist-8 pipeline --
        {
            u64 acc[4][2];
            #pragma unroll
            for (int p = 0; p < 4; p++) { acc[p][0] = bq0; acc[p][1] = bq1; }

            // recurrent part, k = 0..255
            const float2* rk2 = (const float2*)lstmRK;
            float2 a0 = rk2[t],        a1 = rk2[512 + t];
            float2 a2 = rk2[1024 + t], a3 = rk2[1536 + t];
            float2 c0 = rk2[2048 + t], c1 = rk2[2560 + t];
            float2 c2 = rk2[3072 + t], c3 = rk2[3584 + t];
            #pragma unroll 2
            for (int k = 0; k < Hh; k += 8) {
                int kn = (k + 8) & 255;
                float2 na0 = rk2[kn * 512 + t],       na1 = rk2[(kn + 1) * 512 + t];
                float2 na2 = rk2[(kn + 2) * 512 + t], na3 = rk2[(kn + 3) * 512 + t];
                eblk<512>(sm.hp, k,     a0, a1, acc);
                eblk<512>(sm.hp, k + 2, a2, a3, acc);
                int km = (k + 12) & 255;
                float2 nc0 = rk2[km * 512 + t],       nc1 = rk2[(km + 1) * 512 + t];
                float2 nc2 = rk2[(km + 2) * 512 + t], nc3 = rk2[(km + 3) * 512 + t];
                eblk<512>(sm.hp, k + 4, c0, c1, acc);
                eblk<512>(sm.hp, k + 6, c2, c3, acc);
                a0 = na0; a1 = na1; a2 = na2; a3 = na3;
                c0 = nc0; c1 = nc1; c2 = nc2; c3 = nc3;
            }

            // c_c part, k = 0..63 (lstmK rows 0..63)
            const float2* kk2 = (const float2*)lstmK;
            a0 = kk2[t];        a1 = kk2[512 + t];
            a2 = kk2[1024 + t]; a3 = kk2[1536 + t];
            c0 = kk2[2048 + t]; c1 = kk2[2560 + t];
            c2 = kk2[3072 + t]; c3 = kk2[3584 + t];
            #pragma unroll 2
            for (int k = 0; k < Dd; k += 8) {
                int kn = (k + 8) & 63;
                float2 na0 = kk2[kn * 512 + t],       na1 = kk2[(kn + 1) * 512 + t];
                float2 na2 = kk2[(kn + 2) * 512 + t], na3 = kk2[(kn + 3) * 512 + t];
                eblk<128>(sm.ccp, k,     a0, a1, acc);
                eblk<128>(sm.ccp, k + 2, a2, a3, acc);
                int km = (k + 12) & 63;
                float2 nc0 = kk2[km * 512 + t],       nc1 = kk2[(km + 1) * 512 + t];
                float2 nc2 = kk2[(km + 2) * 512 + t], nc3 = kk2[(km + 3) * 512 + t];
                eblk<128>(sm.ccp, k + 4, c0, c1, acc);
                eblk<128>(sm.ccp, k + 6, c2, c3, acc);
                a0 = na0; a1 = na1; a2 = na2; a3 = na3;
                c0 = nc0; c1 = nc1; c2 = nc2; c3 = nc3;
            }

            // m part, k = 0..63 (lstmK rows 64..127)
            const float2* km2 = kk2 + 64 * 512;
            a0 = km2[t];        a1 = km2[512 + t];
            a2 = km2[1024 + t]; a3 = km2[1536 + t];
            c0 = km2[2048 + t]; c1 = km2[2560 + t];
            c2 = km2[3072 + t]; c3 = km2[3584 + t];
            #pragma unroll 2
            for (int k = 0; k < Dd; k += 8) {
                int kn = (k + 8) & 63;
                float2 na0 = km2[kn * 512 + t],       na1 = km2[(kn + 1) * 512 + t];
                float2 na2 = km2[(kn + 2) * 512 + t], na3 = km2[(kn + 3) * 512 + t];
                eblk<128>(sm.mp, k,     a0, a1, acc);
                eblk<128>(sm.mp, k + 2, a2, a3, acc);
                int km_ = (k + 12) & 63;
                float2 nc0 = km2[km_ * 512 + t],       nc1 = km2[(km_ + 1) * 512 + t];
                float2 nc2 = km2[(km_ + 2) * 512 + t], nc3 = km2[(km_ + 3) * 512 + t];
                eblk<128>(sm.mp, k + 4, c0, c1, acc);
                eblk<128>(sm.mp, k + 6, c2, c3, acc);
                a0 = na0; a1 = na1; a2 = na2; a3 = na3;
                c0 = nc0; c1 = nc1; c2 = nc2; c3 = nc3;
            }

            const int gate = t >> 7;
            #pragma unroll
            for (int p = 0; p < 4; p++) {
                #pragma unroll
                for (int q = 0; q < 2; q++) {
                    float v0, v1; upk2(acc[p][q], v0, v1);
                    float b0f, b1f;
                    if (gate == 2) { b0f = tanhfast(v0); b1f = tanhfast(v1); }
                    else           { b0f = sigf(v0);     b1f = sigf(v1);     }
                    int col = 2 * t + q;
                    *(float2*)(sm.zp + p * 2048 + col * 2) = make_float2(b0f, b1f);
                }
            }
        }
        __syncthreads();

        // ---- P5: wg0 {c,h update + fused next-step decay} | wg1 {commit} ----
        if (t < 256) {
            int r = t >> 5;
            int p = r >> 1, par = r & 1;
            int cb = (t & 31) * 8;
            bool last = (step == Tt - 1);
            float4 gA = *(const float4*)(sm.gh + r * Hh + cb);
            float4 gB = *(const float4*)(sm.gh + r * Hh + cb + 4);
            float gv8[8] = {gA.x, gA.y, gA.z, gA.w, gB.x, gB.y, gB.z, gB.w};
            #pragma unroll
            for (int cc = 0; cc < 8; cc++) {
                int c = cb + cc;
                float iv = sm.zp[p * 2048 + (0 * Hh + c) * 2 + par];
                float fv = sm.zp[p * 2048 + (1 * Hh + c) * 2 + par];
                float gg = sm.zp[p * 2048 + (2 * Hh + c) * 2 + par];
                float ov = sm.zp[p * 2048 + (3 * Hh + c) * 2 + par];
                float cold = sm.cs[r * Hh + c];
                float cnew = fv * cold + iv * gg;
                sm.cs[r * Hh + c] = cnew;
                float hh = ov * tanhfast(cnew);
                if (!last) hh *= gv8[cc];
                sm.hp[p * 512 + c * 2 + par] = hh;
            }
        } else if (step + 1 < Tt) {
            const int u = t - 256;
            #pragma unroll
            for (int s = 0; s < 2; s++) {
                int e = u + s * 256;
                int r = e >> 6, jj = e & 63;
                sm.xs[e] = pf_x[s]; sm.ms[e] = pf_m[s];
                sm.mp[(r >> 1) * 128 + jj * 2 + (r & 1)] = pf_m[s];
            }
            int j = u & 63, rp = u >> 6;
            *(float2*)(sm.alp + rp * 128 + j * 2) = make_float2(pf_a0, pf_a1);
        }
        __syncthreads();
    }

    // ---- final: y = h @ out_W + out_b ----
    {
        int w = t >> 5, lane = t & 31;
        if (w < MB) {
            float s = 0.f;
            for (int k = lane; k < Hh; k += 32)
                s += sm.hp[(w >> 1) * 512 + k * 2 + (w & 1)] * outW[k];
            #pragma unroll
            for (int o = 16; o > 0; o >>= 1)
                s += __shfl_down_sync(0xffffffffu, s, o);
            if (lane == 0) yout[b0 + w] = s + outB[0];
        }
    }
}

// ================================ launcher ================================

extern "C" void kernel_launch(void* const* d_in, const int* in_sizes, int n_in,
                              void* d_out, int out_size) {
    const float* values = (const float*)d_in[0];
    const float* masks  = (const float*)d_in[1];
    const float* deltas = (const float*)d_in[2];
    const float* tdhW   = (const float*)d_in[3];
    const float* tdhB   = (const float*)d_in[4];
    const float* tdxW   = (const float*)d_in[5];
    const float* tdxB   = (const float*)d_in[6];
    const float* histW  = (const float*)d_in[7];
    const float* histB  = (const float*)d_in[8];
    const float* frW    = (const float*)d_in[9];
    const float* frB    = (const float*)d_in[10];
    const float* wcW    = (const float*)d_in[11];
    const float* wcB    = (const float*)d_in[12];
    const float* lstmK  = (const float*)d_in[13];
    const float* lstmRK = (const float*)d_in[14];
    const float* lstmB  = (const float*)d_in[15];
    const float* outW   = (const float*)d_in[16];
    const float* outB   = (const float*)d_in[17];

    float* yout   = (float*)d_out;       // y_h [B,1] first
    float* impout = yout + Bsz;          // imputations [B,T,D]

    transpose_kernel<<<(Hh * Dd + Dd * Dd + 255) / 256, 256>>>(tdhW, tdxW);
    pre_ga_kernel<<<Bsz * Tt / 8, 256>>>(deltas, masks, tdhB, tdxB, wcW, wcB);

    cudaFuncSetAttribute(rits_kernel, cudaFuncAttributeMaxDynamicSharedMemorySize,
                         (int)sizeof(Smem));
    rits_kernel<<<GRID, NT, sizeof(Smem)>>>(
        values, masks, histW, histB, frW, frB,
        lstmK, lstmRK, lstmB, outW, outB, yout, impout);
}

// round 11
// speedup vs baseline: 1.1518x; 1.0134x over previous
#include <cuda_runtime.h>
#include <cuda_fp16.h>
#include <cstdint>

#define Bsz 1024
#define Tt  128
#define Dd  64
#define Hh  256
#define MB  8
#define NT  512
#define GRID 128

typedef unsigned long long u64;

// ------------------- device scratch -------------------
__device__ float tdhT_g[Dd * Hh];        // td_h_W^T  [k][c]
__device__ float tdxT_g[Dd * Dd];        // td_x_W^T  [k][j]
__device__ float Gh_g[Bsz * Tt * Hh];    // gamma_h   [b*T+t][256]
__device__ float alpha_g[Bsz * Tt * Dd]; // alpha     [b*T+t][64]
__device__ __half WEHrk_g[Hh * 1024];    // lstmRK in fp16, same layout
__device__ __half WEHk_g[2 * Dd * 1024]; // lstmK  in fp16, same layout

__device__ __forceinline__ u64 dup2(float w) {
    u64 r; asm("mov.b64 %0, {%1,%1};" : "=l"(r) : "f"(w)); return r;
}
__device__ __forceinline__ void upk2(u64 v, float& lo, float& hi) {
    asm("mov.b64 {%0,%1}, %2;" : "=f"(lo), "=f"(hi) : "l"(v));
}
__device__ __forceinline__ u64 fma2(u64 a, u64 b, u64 c) {
    u64 d; asm("fma.rn.f32x2 %0, %1, %2, %3;" : "=l"(d) : "l"(a), "l"(b), "l"(c)); return d;
}
__device__ __forceinline__ float sigf(float x) {
    return __fdividef(1.f, 1.f + __expf(-x));
}
__device__ __forceinline__ float tanhfast(float x) {
    return __fdividef(2.f, 1.f + __expf(-2.f * x)) - 1.f;
}

// ============================ precompute kernels ============================

__global__ void transpose_kernel(const float* __restrict__ tdhW,
                                 const float* __restrict__ tdxW) {
    int idx = blockIdx.x * 256 + threadIdx.x;
    if (idx < Hh * Dd) {                       // tdhW (256,64) -> [k][c]
        int c = idx >> 6, k = idx & 63;
        tdhT_g[k * Hh + c] = tdhW[idx];
    } else if (idx < Hh * Dd + Dd * Dd) {      // tdxW (64,64) -> [k][j]
        int e = idx - Hh * Dd;
        int j = e >> 6, k = e & 63;
        tdxT_g[k * Dd + j] = tdxW[e];
    }
}

// convert LSTM weights to fp16 (weights only; accumulation stays fp32)
__global__ void pack_h_kernel(const float* __restrict__ rk,
                              const float* __restrict__ kk) {
    int idx = blockIdx.x * 256 + threadIdx.x;   // 384*1024 total
    if (idx < Hh * 1024)
        WEHrk_g[idx] = __float2half(rk[idx]);
    else if (idx < Hh * 1024 + 2 * Dd * 1024) {
        int e = idx - Hh * 1024;
        WEHk_g[e] = __float2half(kk[e]);
    }
}

// merged: gamma_h AND (gamma_x -> alpha) for 8 rows/CTA (shares delta/mask loads)
__global__ void __launch_bounds__(256) pre_ga_kernel(
    const float* __restrict__ deltas, const float* __restrict__ masks,
    const float* __restrict__ tdhB, const float* __restrict__ tdxB,
    const float* __restrict__ wcW, const float* __restrict__ wcB)
{
    __shared__ float dp[4 * Dd * 2], mp[4 * Dd * 2], gxp[4 * Dd * 2];
    const int tid = threadIdx.x;
    const int row0 = blockIdx.x * 8;
    for (int e = tid; e < 8 * Dd; e += 256) {
        int r = e >> 6, k = e & 63;
        dp[(r >> 1) * 128 + k * 2 + (r & 1)] = deltas[(row0 + r) * Dd + k];
        mp[(r >> 1) * 128 + k * 2 + (r & 1)] = masks[(row0 + r) * Dd + k];
    }
    __syncthreads();

    // ---- gamma_h: each thread one column c ----
    {
        const int c = tid;
        u64 a[4];
        #pragma unroll
        for (int p = 0; p < 4; p++) a[p] = 0ULL;
        #pragma unroll 4
        for (int k = 0; k < Dd; k++) {
            u64 wd = dup2(tdhT_g[k * Hh + c]);
            #pragma unroll
            for (int p = 0; p < 4; p++)
                a[p] = fma2(*(const u64*)(dp + p * 128 + k * 2), wd, a[p]);
        }
        float bb = tdhB[c];
        #pragma unroll
        for (int p = 0; p < 4; p++) {
            float a0, a1; upk2(a[p], a0, a1);
            Gh_g[(row0 + 2 * p)     * Hh + c] = __expf(-fmaxf(a0 + bb, 0.f));
            Gh_g[(row0 + 2 * p + 1) * Hh + c] = __expf(-fmaxf(a1 + bb, 0.f));
        }
    }

    // ---- gamma_x then alpha ----
    const int j = tid & 63, pg = tid >> 6;
    u64 g = dup2(tdxB[j]);
    #pragma unroll 4
    for (int k = 0; k < Dd; k++)
        g = fma2(*(const u64*)(dp + pg * 128 + k * 2), dup2(tdxT_g[k * Dd + j]), g);
    float g0, g1; upk2(g, g0, g1);
    gxp[pg * 128 + j * 2 + 0] = __expf(-fmaxf(g0, 0.f));
    gxp[pg * 128 + j * 2 + 1] = __expf(-fmaxf(g1, 0.f));
    __syncthreads();
    u64 al = dup2(wcB[j]);
    #pragma unroll 4
    for (int k = 0; k < Dd; k++) {
        al = fma2(*(const u64*)(gxp + pg * 128 + k * 2), dup2(wcW[k * Dd + j]), al);
        al = fma2(*(const u64*)(mp  + pg * 128 + k * 2), dup2(wcW[(Dd + k) * Dd + j]), al);
    }
    float a0, a1; upk2(al, a0, a1);
    alpha_g[(row0 + 2 * pg)     * Dd + j] = a0;
    alpha_g[(row0 + 2 * pg + 1) * Dd + j] = a1;
}

// ============================ main recurrent kernel ============================

struct __align__(16) Smem {
    float hist[Hh * Dd];      // 64 KB
    float frT[Dd * Dd];       // 16 KB
    float hp[4 * 2 * Hh];     //  8 KB  h paired [p][c*2+par]
    float cs[MB * Hh];        //  8 KB
    float zp[4 * 2 * 4 * Hh]; // 32 KB  gate acts (alias: x_h partials)
    float gh[MB * Hh];        //  8 KB  G_h[t+1] staging [r][c]
    float xs[MB * Dd], ms[MB * Dd];
    float mp[4 * 2 * Dd];     // paired m  [p][k*2+par]
    float alp[4 * 2 * Dd];
    float xcp[4 * 2 * Dd], xhp[4 * 2 * Dd], ccp[4 * 2 * Dd];
    float hist_b[Dd], fr_b[Dd];
};

// fp16 weight pair (2 cols, 1 row) per argument, fp32 math
template <int STRIDE>
__device__ __forceinline__ void eblkh(const float* src, int k0,
                                      uint32_t w0, uint32_t w1, u64 (&acc)[4][2]) {
    float2 f0 = __half22float2(*reinterpret_cast<const __half2*>(&w0));
    float2 f1 = __half22float2(*reinterpret_cast<const __half2*>(&w1));
    u64 wa0 = dup2(f0.x), wb0 = dup2(f0.y);
    u64 wa1 = dup2(f1.x), wb1 = dup2(f1.y);
    #pragma unroll
    for (int p = 0; p < 4; p++) {
        float4 hv = *(const float4*)(src + p * STRIDE + k0 * 2);
        u64 h0 = ((const u64*)&hv)[0];
        u64 h1 = ((const u64*)&hv)[1];
        acc[p][0] = fma2(h0, wa0, acc[p][0]);
        acc[p][1] = fma2(h0, wb0, acc[p][1]);
        acc[p][0] = fma2(h1, wa1, acc[p][0]);
        acc[p][1] = fma2(h1, wb1, acc[p][1]);
    }
}

__global__ void __launch_bounds__(NT, 1) rits_kernel(
    const float* __restrict__ values, const float* __restrict__ masks,
    const float* __restrict__ histW, const float* __restrict__ histB,
    const float* __restrict__ frW, const float* __restrict__ frB,
    const float* __restrict__ lstmB,
    const float* __restrict__ outW, const float* __restrict__ outB,
    float* __restrict__ yout, float* __restrict__ impout)
{
    extern __shared__ char smem_raw[];
    Smem& sm = *reinterpret_cast<Smem*>(smem_raw);

    const int t  = threadIdx.x;
    const int b0 = blockIdx.x * MB;

    // ---- stage resident weights & init state ----
    for (int e = t; e < Hh * Dd; e += NT) sm.hist[e] = histW[e];
    for (int e = t; e < Dd * Dd; e += NT) {
        int k = e >> 6, jj = e & 63;
        sm.frT[e] = frW[jj * Dd + k];
    }
    if (t < Dd) { sm.hist_b[t] = histB[t]; sm.fr_b[t] = frB[t]; }
    for (int e = t; e < MB * Hh; e += NT) sm.cs[e] = 0.f;
    for (int e = t; e < 4 * 2 * Hh; e += NT) sm.hp[e] = 0.f;
    {   // step-0 inputs + alpha[0]
        int r = t >> 6, jj = t & 63;
        int off = ((b0 + r) * Tt + 0) * Dd + jj;
        float xv = values[off], mv = masks[off];
        sm.xs[t] = xv; sm.ms[t] = mv;
        sm.mp[(r >> 1) * 128 + jj * 2 + (r & 1)] = mv;
        int j = t & 63, p = (t >> 6) & 3, par = t >> 8;
        sm.alp[p * 128 + j * 2 + par] = alpha_g[((b0 + 2 * p + par) * Tt + 0) * Dd + j];
    }
    // LSTM bias for this thread's two output columns (cols 2t, 2t+1)
    const u64 bq0 = dup2(lstmB[2 * t]);
    const u64 bq1 = dup2(lstmB[2 * t + 1]);
    __syncthreads();

    float pf_x[2], pf_m[2], pf_a0, pf_a1;   // wg1 prefetch regs

    for (int step = 0; step < Tt; ++step) {
        // ---- P1 (all): x_h partials, k-split 8-way, into zp alias ----
        float2* cpart = (float2*)sm.zp;
        {
            const int j = t & 63, kq = t >> 6;
            u64 a[4];
            #pragma unroll
            for (int p = 0; p < 4; p++) a[p] = 0ULL;
            const int k0 = kq * 32;
            #pragma unroll 4
            for (int kk = 0; kk < 32; kk++) {
                int k = k0 + kk;
                u64 wd = dup2(sm.hist[k * Dd + j]);
                #pragma unroll
                for (int p = 0; p < 4; p++)
                    a[p] = fma2(*(const u64*)(sm.hp + p * 512 + k * 2), wd, a[p]);
            }
            #pragma unroll
            for (int p = 0; p < 4; p++) {
                float a0, a1; upk2(a[p], a0, a1);
                cpart[(kq * 4 + p) * 64 + j] = make_float2(a0, a1);
            }
        }
        __syncthreads();

        // ---- P3: wg0 {reduce -> x_c; z_h -> c_c -> impout} | wg1 {prefetch} --
        if (t < 256) {
            const int j = t & 63, p = t >> 6;
            const float* cp = (const float*)cpart;
            float xh[2];
            #pragma unroll
            for (int par = 0; par < 2; par++) {
                float s = 0.f;
                #pragma unroll
                for (int kq = 0; kq < 8; kq++)
                    s += cp[((kq * 4 + p) * 64 + j) * 2 + par];
                xh[par] = s + sm.hist_b[j];
                int r = 2 * p + par;
                float m = sm.ms[r * Dd + j], x = sm.xs[r * Dd + j];
                float xc = m * x + (1.f - m) * xh[par];
                sm.xcp[p * 128 + j * 2 + par] = xc;
                sm.xhp[p * 128 + j * 2 + par] = xh[par];
            }
            asm volatile("bar.sync 1, 256;" ::: "memory");
            u64 z = dup2(sm.fr_b[j]);
            #pragma unroll 4
            for (int k = 0; k < Dd; k++)
                z = fma2(*(const u64*)(sm.xcp + p * 128 + k * 2),
                         dup2(sm.frT[k * Dd + j]), z);
            float z0, z1; upk2(z, z0, z1);
            float2 al = *(const float2*)(sm.alp + p * 128 + j * 2);
            int r0 = 2 * p, r1 = r0 + 1;
            float m0 = sm.ms[r0 * Dd + j], m1 = sm.ms[r1 * Dd + j];
            float x0 = sm.xs[r0 * Dd + j], x1 = sm.xs[r1 * Dd + j];
            float ch0 = al.x * z0 + (1.f - al.x) * xh[0];
            float ch1 = al.y * z1 + (1.f - al.y) * xh[1];
            float cc0 = m0 * x0 + (1.f - m0) * ch0;
            float cc1 = m1 * x1 + (1.f - m1) * ch1;
            *(float2*)(sm.ccp + p * 128 + j * 2) = make_float2(cc0, cc1);
            impout[(r0 + b0) * Tt * Dd + step * Dd + j] = cc0;
            impout[(r1 + b0) * Tt * Dd + step * Dd + j] = cc1;
        } else if (step + 1 < Tt) {
            const int u = t - 256;
            #pragma unroll
            for (int s = 0; s < 2; s++) {
                int e = u + s * 256;
                int r = e >> 6, jj = e & 63;
                int off = ((b0 + r) * Tt + (step + 1)) * Dd + jj;
                pf_x[s] = values[off]; pf_m[s] = masks[off];
            }
            {
                int j = u & 63, rp = u >> 6;
                pf_a0 = alpha_g[((b0 + 2 * rp)     * Tt + step + 1) * Dd + j];
                pf_a1 = alpha_g[((b0 + 2 * rp + 1) * Tt + step + 1) * Dd + j];
            }
            {
                int r = u >> 5, c0 = (u & 31) * 8;
                const float* gsrc = Gh_g + ((b0 + r) * Tt + (step + 1)) * Hh + c0;
                float4 g0 = *(const float4*)gsrc;
                float4 g1 = *(const float4*)(gsrc + 4);
                *(float4*)(sm.gh + r * Hh + c0)     = g0;
                *(float4*)(sm.gh + r * Hh + c0 + 4) = g1;
            }
        }
        __syncthreads();

        // ---- P4 (all): z = b + h@Wrk + c_c@Wk_cc + m@Wk_m ; fp16 weights ----
        {
            u64 acc[4][2];
            #pragma unroll
            for (int p = 0; p < 4; p++) { acc[p][0] = bq0; acc[p][1] = bq1; }

            // recurrent part, k = 0..255 (fp16 weights, row stride 512 u32)
            const uint32_t* rk2 = (const uint32_t*)WEHrk_g;
            uint32_t a0 = rk2[t],        a1 = rk2[512 + t];
            uint32_t a2 = rk2[1024 + t], a3 = rk2[1536 + t];
            uint32_t c0 = rk2[2048 + t], c1 = rk2[2560 + t];
            uint32_t c2 = rk2[3072 + t], c3 = rk2[3584 + t];
            #pragma unroll 2
            for (int k = 0; k < Hh; k += 8) {
                int kn = (k + 8) & 255;
                uint32_t na0 = rk2[kn * 512 + t],       na1 = rk2[(kn + 1) * 512 + t];
                uint32_t na2 = rk2[(kn + 2) * 512 + t], na3 = rk2[(kn + 3) * 512 + t];
                eblkh<512>(sm.hp, k,     a0, a1, acc);
                eblkh<512>(sm.hp, k + 2, a2, a3, acc);
                int km = (k + 12) & 255;
                uint32_t nc0 = rk2[km * 512 + t],       nc1 = rk2[(km + 1) * 512 + t];
                uint32_t nc2 = rk2[(km + 2) * 512 + t], nc3 = rk2[(km + 3) * 512 + t];
                eblkh<512>(sm.hp, k + 4, c0, c1, acc);
                eblkh<512>(sm.hp, k + 6, c2, c3, acc);
                a0 = na0; a1 = na1; a2 = na2; a3 = na3;
                c0 = nc0; c1 = nc1; c2 = nc2; c3 = nc3;
            }

            // c_c part, k = 0..63 (WEHk rows 0..63)
            const uint32_t* kk2 = (const uint32_t*)WEHk_g;
            a0 = kk2[t];        a1 = kk2[512 + t];
            a2 = kk2[1024 + t]; a3 = kk2[1536 + t];
            c0 = kk2[2048 + t]; c1 = kk2[2560 + t];
            c2 = kk2[3072 + t]; c3 = kk2[3584 + t];
            #pragma unroll 2
            for (int k = 0; k < Dd; k += 8) {
                int kn = (k + 8) & 63;
                uint32_t na0 = kk2[kn * 512 + t],       na1 = kk2[(kn + 1) * 512 + t];
                uint32_t na2 = kk2[(kn + 2) * 512 + t], na3 = kk2[(kn + 3) * 512 + t];
                eblkh<128>(sm.ccp, k,     a0, a1, acc);
                eblkh<128>(sm.ccp, k + 2, a2, a3, acc);
                int km = (k + 12) & 63;
                uint32_t nc0 = kk2[km * 512 + t],       nc1 = kk2[(km + 1) * 512 + t];
                uint32_t nc2 = kk2[(km + 2) * 512 + t], nc3 = kk2[(km + 3) * 512 + t];
                eblkh<128>(sm.ccp, k + 4, c0, c1, acc);
                eblkh<128>(sm.ccp, k + 6, c2, c3, acc);
                a0 = na0; a1 = na1; a2 = na2; a3 = na3;
                c0 = nc0; c1 = nc1; c2 = nc2; c3 = nc3;
            }

            // m part, k = 0..63 (WEHk rows 64..127)
            const uint32_t* km2 = kk2 + 64 * 512;
            a0 = km2[t];        a1 = km2[512 + t];
            a2 = km2[1024 + t]; a3 = km2[1536 + t];
            c0 = km2[2048 + t]; c1 = km2[2560 + t];
            c2 = km2[3072 + t]; c3 = km2[3584 + t];
            #pragma unroll 2
            for (int k = 0; k < Dd; k += 8) {
                int kn = (k + 8) & 63;
                uint32_t na0 = km2[kn * 512 + t],       na1 = km2[(kn + 1) * 512 + t];
                uint32_t na2 = km2[(kn + 2) * 512 + t], na3 = km2[(kn + 3) * 512 + t];
                eblkh<128>(sm.mp, k,     a0, a1, acc);
                eblkh<128>(sm.mp, k + 2, a2, a3, acc);
                int km_ = (k + 12) & 63;
                uint32_t nc0 = km2[km_ * 512 + t],       nc1 = km2[(km_ + 1) * 512 + t];
                uint32_t nc2 = km2[(km_ + 2) * 512 + t], nc3 = km2[(km_ + 3) * 512 + t];
                eblkh<128>(sm.mp, k + 4, c0, c1, acc);
                eblkh<128>(sm.mp, k + 6, c2, c3, acc);
                a0 = na0; a1 = na1; a2 = na2; a3 = na3;
                c0 = nc0; c1 = nc1; c2 = nc2; c3 = nc3;
            }

            const int gate = t >> 7;
            #pragma unroll
            for (int p = 0; p < 4; p++) {
                #pragma unroll
                for (int q = 0; q < 2; q++) {
                    float v0, v1; upk2(acc[p][q], v0, v1);
                    float b0f, b1f;
                    if (gate == 2) { b0f = tanhfast(v0); b1f = tanhfast(v1); }
                    else           { b0f = sigf(v0);     b1f = sigf(v1);     }
                    int col = 2 * t + q;
                    *(float2*)(sm.zp + p * 2048 + col * 2) = make_float2(b0f, b1f);
                }
            }
        }
        __syncthreads();

        // ---- P5: wg0 {c,h update + fused next-step decay} | wg1 {commit} ----
        if (t < 256) {
            int r = t >> 5;
            int p = r >> 1, par = r & 1;
            int cb = (t & 31) * 8;
            bool last = (step == Tt - 1);
            float4 gA = *(const float4*)(sm.gh + r * Hh + cb);
            float4 gB = *(const float4*)(sm.gh + r * Hh + cb + 4);
            float gv8[8] = {gA.x, gA.y, gA.z, gA.w, gB.x, gB.y, gB.z, gB.w};
            #pragma unroll
            for (int cc = 0; cc < 8; cc++) {
                int c = cb + cc;
                float iv = sm.zp[p * 2048 + (0 * Hh + c) * 2 + par];
                float fv = sm.zp[p * 2048 + (1 * Hh + c) * 2 + par];
                float gg = sm.zp[p * 2048 + (2 * Hh + c) * 2 + par];
                float ov = sm.zp[p * 2048 + (3 * Hh + c) * 2 + par];
                float cold = sm.cs[r * Hh + c];
                float cnew = fv * cold + iv * gg;
                sm.cs[r * Hh + c] = cnew;
                float hh = ov * tanhfast(cnew);
                if (!last) hh *= gv8[cc];
                sm.hp[p * 512 + c * 2 + par] = hh;
            }
        } else if (step + 1 < Tt) {
            const int u = t - 256;
            #pragma unroll
            for (int s = 0; s < 2; s++) {
                int e = u + s * 256;
                int r = e >> 6, jj = e & 63;
                sm.xs[e] = pf_x[s]; sm.ms[e] = pf_m[s];
                sm.mp[(r >> 1) * 128 + jj * 2 + (r & 1)] = pf_m[s];
            }
            int j = u & 63, rp = u >> 6;
            *(float2*)(sm.alp + rp * 128 + j * 2) = make_float2(pf_a0, pf_a1);
        }
        __syncthreads();
    }

    // ---- final: y = h @ out_W + out_b ----
    {
        int w = t >> 5, lane = t & 31;
        if (w < MB) {
            float s = 0.f;
            for (int k = lane; k < Hh; k += 32)
                s += sm.hp[(w >> 1) * 512 + k * 2 + (w & 1)] * outW[k];
            #pragma unroll
            for (int o = 16; o > 0; o >>= 1)
                s += __shfl_down_sync(0xffffffffu, s, o);
            if (lane == 0) yout[b0 + w] = s + outB[0];
        }
    }
}

// ================================ launcher ================================

extern "C" void kernel_launch(void* const* d_in, const int* in_sizes, int n_in,
                              void* d_out, int out_size) {
    const float* values = (const float*)d_in[0];
    const float* masks  = (const float*)d_in[1];
    const float* deltas = (const float*)d_in[2];
    const float* tdhW   = (const float*)d_in[3];
    const float* tdhB   = (const float*)d_in[4];
    const float* tdxW   = (const float*)d_in[5];
    const float* tdxB   = (const float*)d_in[6];
    const float* histW  = (const float*)d_in[7];
    const float* histB  = (const float*)d_in[8];
    const float* frW    = (const float*)d_in[9];
    const float* frB    = (const float*)d_in[10];
    const float* wcW    = (const float*)d_in[11];
    const float* wcB    = (const float*)d_in[12];
    const float* lstmK  = (const float*)d_in[13];
    const float* lstmRK = (const float*)d_in[14];
    const float* lstmB  = (const float*)d_in[15];
    const float* outW   = (const float*)d_in[16];
    const float* outB   = (const float*)d_in[17];

    float* yout   = (float*)d_out;       // y_h [B,1] first
    float* impout = yout + Bsz;          // imputations [B,T,D]

    transpose_kernel<<<(Hh * Dd + Dd * Dd + 255) / 256, 256>>>(tdhW, tdxW);
    pack_h_kernel<<<(384 * 1024 + 255) / 256, 256>>>(lstmRK, lstmK);
    pre_ga_kernel<<<Bsz * Tt / 8, 256>>>(deltas, masks, tdhB, tdxB, wcW, wcB);

    cudaFuncSetAttribute(rits_kernel, cudaFuncAttributeMaxDynamicSharedMemorySize,
                         (int)sizeof(Smem));
    rits_kernel<<<GRID, NT, sizeof(Smem)>>>(
        values, masks, histW, histB, frW, frB,
        lstmB, outW, outB, yout, impout);
}